// round 10
// baseline (speedup 1.0000x reference)
#include <cuda_runtime.h>
#include <cuda_bf16.h>

#define BMAX 16384

typedef unsigned long long u64;

// Scratch (static device globals — no allocation).
// Pair-interleaved layout: g_U4[p][o2][bh] (p<8, o2<10, bh<B/2), float4 =
//   { U[2bh][p][2o2], U[2bh][p][2o2+1], U[2bh+1][p][2o2], U[2bh+1][p][2o2+1] }
// (b_feat folded into U). Same for V. 10.5 MB each -> L2-resident.
__device__ float4 g_U4[8 * 10 * (BMAX / 2)];
__device__ float4 g_V4[8 * 10 * (BMAX / 2)];
// per-position relu(final) values, summed in groups of 7 by k3
__device__ float g_S[BMAX * 56];

// PHASE_LANES = [[1,3],[5,7],[0,2],[4,6],[0,1],[2,3],[4,5],[6,7]]
__device__ const int d_PLa[8] = {1, 5, 0, 4, 0, 2, 4, 6};
__device__ const int d_PLb[8] = {3, 7, 2, 6, 1, 3, 5, 7};

__device__ __forceinline__ float sigmoidf(float x) {
    return __fdividef(1.0f, 1.0f + __expf(-x));
}
__device__ __forceinline__ u64 pk2(float lo, float hi) {
    u64 r;
    asm("mov.b64 %0, {%1, %2};" : "=l"(r) : "f"(lo), "f"(hi));
    return r;
}
__device__ __forceinline__ void upk2(float& lo, float& hi, u64 v) {
    asm("mov.b64 {%0, %1}, %2;" : "=f"(lo), "=f"(hi) : "l"(v));
}
__device__ __forceinline__ u64 f2fma(u64 a, u64 b, u64 c) {
    u64 d;
    asm("fma.rn.f32x2 %0, %1, %2, %3;" : "=l"(d) : "l"(a), "l"(b), "l"(c));
    return d;
}
__device__ __forceinline__ u64 f2mul(u64 a, u64 b) {
    u64 d;
    asm("mul.rn.f32x2 %0, %1, %2;" : "=l"(d) : "l"(a), "l"(b));
    return d;
}

// ---------------------------------------------------------------------------
// Kernel 1: grid (B/256, 8); p = blockIdx.y (lane-pair phase), b fast across
// lanes. Computes press[16], then packed (U,V) projections, stores
// pair-interleaved coalesced float2s.
// ---------------------------------------------------------------------------
__global__ void __launch_bounds__(256, 2)
frap_k1(const float* __restrict__ fi,
        const float* __restrict__ emb_phase,
        const float* __restrict__ w_veh,
        const float* __restrict__ b_veh,
        const float* __restrict__ w_line,
        const float* __restrict__ b_line,
        const float* __restrict__ w_feat,
        const float* __restrict__ b_feat,
        int B)
{
    __shared__ __align__(16) float s_wline[128];   // (16,8)
    __shared__ __align__(16) u64   s_wpk[320];     // (20,16): (w_feat[o][c], w_feat[o][16+c])
    __shared__ float s_bline[16];
    __shared__ float s_bfeat[20];
    __shared__ float s_emb[8];
    __shared__ float s_wv[4], s_bv[4];

    int tx = threadIdx.x;
    for (int idx = tx; idx < 128; idx += 256) s_wline[idx] = w_line[idx];
    for (int idx = tx; idx < 320; idx += 256) {
        int o = idx >> 4, c = idx & 15;
        s_wpk[idx] = pk2(w_feat[o * 32 + c], w_feat[o * 32 + 16 + c]);
    }
    if (tx < 16) s_bline[tx] = b_line[tx];
    if (tx < 20) s_bfeat[tx] = b_feat[tx];
    if (tx < 8)  s_emb[tx]   = emb_phase[tx];
    if (tx < 4)  { s_wv[tx] = w_veh[tx]; s_bv[tx] = b_veh[tx]; }
    __syncthreads();

    int b = blockIdx.x * 256 + tx;
    if (b >= B) return;
    int p  = blockIdx.y;
    int la = d_PLa[p];
    int lb = d_PLb[p];

    const float* f = fi + (size_t)b * 16;
    float bit_a = f[la],     bit_b = f[lb];
    float veh_a = f[8 + la], veh_b = f[8 + lb];
    int ia = (int)bit_a, ib = (int)bit_b;

    float lineA[8], lineB[8];
#pragma unroll
    for (int d = 0; d < 4; d++) {
        lineA[d]     = sigmoidf(veh_a * s_wv[d] + s_bv[d]);
        lineB[d]     = sigmoidf(veh_b * s_wv[d] + s_bv[d]);
        lineA[4 + d] = sigmoidf(s_emb[ia * 4 + d]);
        lineB[4 + d] = sigmoidf(s_emb[ib * 4 + d]);
    }

    u64 pressd[16];
#pragma unroll
    for (int o = 0; o < 16; o++) {
        const float* w = &s_wline[o * 8];
        float xa = s_bline[o], xb = s_bline[o];
#pragma unroll
        for (int d = 0; d < 8; d++) {
            xa += w[d] * lineA[d];
            xb += w[d] * lineB[d];
        }
        float pr = fmaxf(xa, 0.0f) + fmaxf(xb, 0.0f);
        pressd[o] = pk2(pr, pr);
    }

    int Bh = B >> 1;
    int bh = b >> 1;
    int sub = b & 1;
    float2* stU = (float2*)g_U4;
    float2* stV = (float2*)g_V4;

#pragma unroll
    for (int o2 = 0; o2 < 10; o2++) {
        int oA = 2 * o2, oB = 2 * o2 + 1;
        u64 accA = pk2(s_bfeat[oA], 0.0f);   // (U incl bias, V)
        u64 accB = pk2(s_bfeat[oB], 0.0f);
#pragma unroll
        for (int c = 0; c < 16; c++) {
            accA = f2fma(s_wpk[oA * 16 + c], pressd[c], accA);
            accB = f2fma(s_wpk[oB * 16 + c], pressd[c], accB);
        }
        float uA, vA, uB, vB;
        upk2(uA, vA, accA);
        upk2(uB, vB, accB);
        size_t idx = ((size_t)(p * 10 + o2) * Bh + bh) * 2 + sub;
        stU[idx] = make_float2(uA, uB);
        stV[idx] = make_float2(vA, vB);
    }
}

// ---------------------------------------------------------------------------
// Kernel 2: grid (Bh/256, 56). pair = blockIdx.y (warp-uniform pi/pj),
// thread handles positions t = pair*B + 2*bh, t+1 (coalesced gathers).
// h = relu(U+V)*yc (f32x2-packed over the position pair), then the fused
// comb(20x20)+final layer; writes relu(s) per position to g_S.
// ---------------------------------------------------------------------------
__global__ void __launch_bounds__(256, 2)
frap_k2(const float* __restrict__ emb_const,
        const float* __restrict__ w_const,
        const float* __restrict__ b_const,
        const float* __restrict__ w_comb,
        const float* __restrict__ b_comb,
        const float* __restrict__ w_final,
        const float* __restrict__ b_final,
        const int*   __restrict__ cmask,
        int B)
{
    __shared__ __align__(16) u64 s_ycp[28 * 20];  // (yc[2r][o], yc[2r+1][o])
    __shared__ __align__(16) u64 s_wd[400];       // dup-packed w_comb
    __shared__ u64   s_bcd[20];
    __shared__ float s_wfin[20];
    __shared__ float s_bfin;

    int tx = threadIdx.x;
    for (int idx = tx; idx < 400; idx += 256) {
        float w = w_comb[idx];
        s_wd[idx] = pk2(w, w);
    }
    if (tx < 20) {
        float bc = b_comb[tx];
        s_bcd[tx]  = pk2(bc, bc);
        s_wfin[tx] = w_final[tx];
    }
    if (tx == 0) s_bfin = b_final[0];
    for (int idx = tx; idx < 28 * 20; idx += 256) {
        int r2 = idx / 20;
        int o  = idx - r2 * 20;
        const float* w  = w_const + o * 4;
        const float* e0 = emb_const + cmask[2 * r2] * 4;
        const float* e1 = emb_const + cmask[2 * r2 + 1] * 4;
        float y0 = b_const[o] + w[0]*e0[0] + w[1]*e0[1] + w[2]*e0[2] + w[3]*e0[3];
        float y1 = b_const[o] + w[0]*e1[0] + w[1]*e1[1] + w[2]*e1[2] + w[3]*e1[3];
        s_ycp[idx] = pk2(fmaxf(y0, 0.0f), fmaxf(y1, 0.0f));
    }
    __syncthreads();

    int Bh = B >> 1;
    int bh = blockIdx.x * 256 + tx;
    if (bh >= Bh) return;
    int pair = blockIdx.y;
    int pi = pair / 7;
    int r  = pair - pi * 7;
    int pj = r + (r >= pi ? 1 : 0);

    int t   = pair * B + 2 * bh;     // even
    int rem = t % 56;                // even
    const u64* ycp = s_ycp + (rem >> 1) * 20;

    const float4* Ub = g_U4 + (size_t)pi * 10 * Bh + bh;
    const float4* Vb = g_V4 + (size_t)pj * 10 * Bh + bh;

    u64 Hp[20];
#pragma unroll
    for (int o2 = 0; o2 < 10; o2++) {
        float4 fu = Ub[(size_t)o2 * Bh];
        float4 fv = Vb[(size_t)o2 * Bh];
        float a0 = fmaxf(fu.x + fv.x, 0.0f);   // pos0, o=2o2
        float a1 = fmaxf(fu.z + fv.z, 0.0f);   // pos1, o=2o2
        float b0 = fmaxf(fu.y + fv.y, 0.0f);   // pos0, o=2o2+1
        float b1 = fmaxf(fu.w + fv.w, 0.0f);   // pos1, o=2o2+1
        Hp[2 * o2]     = f2mul(pk2(a0, a1), ycp[2 * o2]);
        Hp[2 * o2 + 1] = f2mul(pk2(b0, b1), ycp[2 * o2 + 1]);
    }

    float s0 = s_bfin, s1 = s_bfin;
#pragma unroll
    for (int o2 = 0; o2 < 20; o2++) {
        const ulonglong2* wr = (const ulonglong2*)(s_wd + o2 * 20);
        u64 a = s_bcd[o2];
#pragma unroll
        for (int k = 0; k < 10; k++) {
            ulonglong2 w2 = wr[k];
            a = f2fma(w2.x, Hp[2 * k],     a);
            a = f2fma(w2.y, Hp[2 * k + 1], a);
        }
        float lo, hi;
        upk2(lo, hi, a);
        float wf = s_wfin[o2];
        s0 += fmaxf(lo, 0.0f) * wf;
        s1 += fmaxf(hi, 0.0f) * wf;
    }

    ((float2*)g_S)[(size_t)pair * Bh + bh] =
        make_float2(fmaxf(s0, 0.0f), fmaxf(s1, 0.0f));
}

// ---------------------------------------------------------------------------
// Kernel 3: out[idx] = sum of g_S[7*idx .. 7*idx+6]
// ---------------------------------------------------------------------------
__global__ void frap_k3(float* __restrict__ out, int n)
{
    int idx = blockIdx.x * blockDim.x + threadIdx.x;
    if (idx >= n) return;
    const float* s = g_S + (size_t)idx * 7;
    float acc = s[0] + s[1] + s[2] + s[3] + s[4] + s[5] + s[6];
    out[idx] = acc;
}

// ---------------------------------------------------------------------------
extern "C" void kernel_launch(void* const* d_in, const int* in_sizes, int n_in,
                              void* d_out, int out_size)
{
    const float* fi        = (const float*)d_in[0];
    const float* emb_phase = (const float*)d_in[1];
    const float* w_veh     = (const float*)d_in[2];
    const float* b_veh     = (const float*)d_in[3];
    const float* w_line    = (const float*)d_in[4];
    const float* b_line    = (const float*)d_in[5];
    const float* emb_const = (const float*)d_in[6];
    const float* w_feat    = (const float*)d_in[7];
    const float* b_feat    = (const float*)d_in[8];
    const float* w_const   = (const float*)d_in[9];
    const float* b_const   = (const float*)d_in[10];
    const float* w_comb    = (const float*)d_in[11];
    const float* b_comb    = (const float*)d_in[12];
    const float* w_final   = (const float*)d_in[13];
    const float* b_final   = (const float*)d_in[14];
    const int*   cmask     = (const int*)d_in[15];

    int B = in_sizes[0] / 16;
    if (B > BMAX) B = BMAX;
    int Bh = B >> 1;

    dim3 grid1((B + 255) / 256, 8);
    dim3 grid2((Bh + 255) / 256, 56);
    int n = B * 8;
    int blocks3 = (n + 255) / 256;

    frap_k1<<<grid1, 256>>>(fi, emb_phase, w_veh, b_veh, w_line, b_line,
                            w_feat, b_feat, B);
    frap_k2<<<grid2, 256>>>(emb_const, w_const, b_const, w_comb, b_comb,
                            w_final, b_final, cmask, B);
    frap_k3<<<blocks3, 256>>>((float*)d_out, n);
}

// round 12
// speedup vs baseline: 1.0052x; 1.0052x over previous
#include <cuda_runtime.h>
#include <cuda_bf16.h>

#define BMAX 16384

typedef unsigned long long u64;

// Scratch (static device globals — no allocation).
// Pair-interleaved layout: g_U4[p][o2][bh] (p<8, o2<10, bh<B/2), float4 =
//   { U[2bh][p][2o2], U[2bh][p][2o2+1], U[2bh+1][p][2o2], U[2bh+1][p][2o2+1] }
// (b_feat folded into U). Same for V. 10.5 MB each -> L2-resident.
__device__ float4 g_U4[8 * 10 * (BMAX / 2)];
__device__ float4 g_V4[8 * 10 * (BMAX / 2)];
// per-position relu(final) values, summed in groups of 7 by k3
__device__ float g_S[BMAX * 56];

// PHASE_LANES = [[1,3],[5,7],[0,2],[4,6],[0,1],[2,3],[4,5],[6,7]]
__device__ const int d_PLa[8] = {1, 5, 0, 4, 0, 2, 4, 6};
__device__ const int d_PLb[8] = {3, 7, 2, 6, 1, 3, 5, 7};

__device__ __forceinline__ float sigmoidf(float x) {
    return __fdividef(1.0f, 1.0f + __expf(-x));
}
__device__ __forceinline__ u64 pk2(float lo, float hi) {
    u64 r;
    asm("mov.b64 %0, {%1, %2};" : "=l"(r) : "f"(lo), "f"(hi));
    return r;
}
__device__ __forceinline__ void upk2(float& lo, float& hi, u64 v) {
    asm("mov.b64 {%0, %1}, %2;" : "=f"(lo), "=f"(hi) : "l"(v));
}
__device__ __forceinline__ u64 f2fma(u64 a, u64 b, u64 c) {
    u64 d;
    asm("fma.rn.f32x2 %0, %1, %2, %3;" : "=l"(d) : "l"(a), "l"(b), "l"(c));
    return d;
}
__device__ __forceinline__ u64 f2mul(u64 a, u64 b) {
    u64 d;
    asm("mul.rn.f32x2 %0, %1, %2;" : "=l"(d) : "l"(a), "l"(b));
    return d;
}

// ---------------------------------------------------------------------------
// Kernel 1: grid (B/256, 8); p = blockIdx.y, b fast across lanes.
// Inputs staged through smem (coalesced); lane MLP packed f32x2 over the
// (laneA, laneB) pair; projection packed f32x2 over (U,V) with LDS.128
// weight reads; sigmoid(emb_phase) precomputed per block.
// ---------------------------------------------------------------------------
__global__ void __launch_bounds__(256, 2)
frap_k1(const float* __restrict__ fi,
        const float* __restrict__ emb_phase,
        const float* __restrict__ w_veh,
        const float* __restrict__ b_veh,
        const float* __restrict__ w_line,
        const float* __restrict__ b_line,
        const float* __restrict__ w_feat,
        const float* __restrict__ b_feat,
        int B)
{
    __shared__ __align__(16) float s_fi[256 * 17];        // padded input tile
    __shared__ __align__(16) u64   s_wline2[128];         // dup-packed (16,8)
    __shared__ __align__(16) ulonglong2 s_wpk2[160];      // [o2][c]: (wA_pk, wB_pk)
    __shared__ u64   s_bline2[16];
    __shared__ float s_bfeat[20];
    __shared__ float s_sge[8];                            // sigmoid(emb_phase)
    __shared__ float s_wv[4], s_bv[4];

    int tx = threadIdx.x;
    int base = blockIdx.x * 256;

    // coalesced staging of the input tile (256 rows x 16 floats)
    {
        const float4* fi4 = (const float4*)(fi + (size_t)base * 16);
        for (int idx = tx; idx < 1024; idx += 256) {
            int r  = idx >> 2;
            int c4 = (idx & 3) * 4;
            if (base + r < B) {
                float4 v = fi4[idx];
                float* d = &s_fi[r * 17 + c4];
                d[0] = v.x; d[1] = v.y; d[2] = v.z; d[3] = v.w;
            }
        }
    }
    for (int idx = tx; idx < 128; idx += 256) {
        float w = w_line[idx];
        s_wline2[idx] = pk2(w, w);
    }
    for (int idx = tx; idx < 160; idx += 256) {
        int o2 = idx >> 4, c = idx & 15;
        ulonglong2 w2;
        w2.x = pk2(w_feat[(2 * o2) * 32 + c],     w_feat[(2 * o2) * 32 + 16 + c]);
        w2.y = pk2(w_feat[(2 * o2 + 1) * 32 + c], w_feat[(2 * o2 + 1) * 32 + 16 + c]);
        s_wpk2[idx] = w2;
    }
    if (tx < 16) { float bl = b_line[tx]; s_bline2[tx] = pk2(bl, bl); }
    if (tx < 20) s_bfeat[tx] = b_feat[tx];
    if (tx < 8)  s_sge[tx]   = sigmoidf(emb_phase[tx]);
    if (tx < 4)  { s_wv[tx] = w_veh[tx]; s_bv[tx] = b_veh[tx]; }
    __syncthreads();

    int b = base + tx;
    if (b >= B) return;
    int p  = blockIdx.y;
    int la = d_PLa[p];
    int lb = d_PLb[p];

    const float* f = &s_fi[tx * 17];
    float bit_a = f[la],     bit_b = f[lb];
    float veh_a = f[8 + la], veh_b = f[8 + lb];
    int ia = (int)bit_a, ib = (int)bit_b;

    // packed line features: (laneA, laneB) per dim
    u64 lp[8];
#pragma unroll
    for (int d = 0; d < 4; d++) {
        lp[d]     = pk2(sigmoidf(veh_a * s_wv[d] + s_bv[d]),
                        sigmoidf(veh_b * s_wv[d] + s_bv[d]));
        lp[4 + d] = pk2(s_sge[ia * 4 + d], s_sge[ib * 4 + d]);
    }

    u64 pressd[16];
#pragma unroll
    for (int o = 0; o < 16; o++) {
        u64 acc = s_bline2[o];
#pragma unroll
        for (int d = 0; d < 8; d++)
            acc = f2fma(s_wline2[o * 8 + d], lp[d], acc);
        float xa, xb;
        upk2(xa, xb, acc);
        float pr = fmaxf(xa, 0.0f) + fmaxf(xb, 0.0f);
        pressd[o] = pk2(pr, pr);
    }

    int Bh = B >> 1;
    int bh = b >> 1;
    int sub = b & 1;
    float2* stU = (float2*)g_U4;
    float2* stV = (float2*)g_V4;

#pragma unroll
    for (int o2 = 0; o2 < 10; o2++) {
        u64 accA = pk2(s_bfeat[2 * o2], 0.0f);       // (U incl bias, V)
        u64 accB = pk2(s_bfeat[2 * o2 + 1], 0.0f);
#pragma unroll
        for (int c = 0; c < 16; c++) {
            ulonglong2 w2 = s_wpk2[o2 * 16 + c];
            accA = f2fma(w2.x, pressd[c], accA);
            accB = f2fma(w2.y, pressd[c], accB);
        }
        float uA, vA, uB, vB;
        upk2(uA, vA, accA);
        upk2(uB, vB, accB);
        size_t idx = ((size_t)(p * 10 + o2) * Bh + bh) * 2 + sub;
        stU[idx] = make_float2(uA, uB);
        stV[idx] = make_float2(vA, vB);
    }
}

// ---------------------------------------------------------------------------
// Kernel 2: grid (Bh/256, 56). pair = blockIdx.y (warp-uniform pi/pj),
// thread handles positions t = pair*B + 2*bh, t+1 (coalesced gathers).
// ---------------------------------------------------------------------------
__global__ void __launch_bounds__(256, 2)
frap_k2(const float* __restrict__ emb_const,
        const float* __restrict__ w_const,
        const float* __restrict__ b_const,
        const float* __restrict__ w_comb,
        const float* __restrict__ b_comb,
        const float* __restrict__ w_final,
        const float* __restrict__ b_final,
        const int*   __restrict__ cmask,
        int B)
{
    __shared__ __align__(16) u64 s_ycp[28 * 20];  // (yc[2r][o], yc[2r+1][o])
    __shared__ __align__(16) u64 s_wd[400];       // dup-packed w_comb
    __shared__ u64   s_bcd[20];
    __shared__ float s_wfin[20];
    __shared__ float s_bfin;

    int tx = threadIdx.x;
    for (int idx = tx; idx < 400; idx += 256) {
        float w = w_comb[idx];
        s_wd[idx] = pk2(w, w);
    }
    if (tx < 20) {
        float bc = b_comb[tx];
        s_bcd[tx]  = pk2(bc, bc);
        s_wfin[tx] = w_final[tx];
    }
    if (tx == 0) s_bfin = b_final[0];
    for (int idx = tx; idx < 28 * 20; idx += 256) {
        int r2 = idx / 20;
        int o  = idx - r2 * 20;
        const float* w  = w_const + o * 4;
        const float* e0 = emb_const + cmask[2 * r2] * 4;
        const float* e1 = emb_const + cmask[2 * r2 + 1] * 4;
        float y0 = b_const[o] + w[0]*e0[0] + w[1]*e0[1] + w[2]*e0[2] + w[3]*e0[3];
        float y1 = b_const[o] + w[0]*e1[0] + w[1]*e1[1] + w[2]*e1[2] + w[3]*e1[3];
        s_ycp[idx] = pk2(fmaxf(y0, 0.0f), fmaxf(y1, 0.0f));
    }
    __syncthreads();

    int Bh = B >> 1;
    int bh = blockIdx.x * 256 + tx;
    if (bh >= Bh) return;
    int pair = blockIdx.y;
    int pi = pair / 7;
    int r  = pair - pi * 7;
    int pj = r + (r >= pi ? 1 : 0);

    int t   = pair * B + 2 * bh;     // even
    int rem = t % 56;                // even
    const u64* ycp = s_ycp + (rem >> 1) * 20;

    const float4* Ub = g_U4 + (size_t)pi * 10 * Bh + bh;
    const float4* Vb = g_V4 + (size_t)pj * 10 * Bh + bh;

    u64 Hp[20];
#pragma unroll
    for (int o2 = 0; o2 < 10; o2++) {
        float4 fu = Ub[(size_t)o2 * Bh];
        float4 fv = Vb[(size_t)o2 * Bh];
        float a0 = fmaxf(fu.x + fv.x, 0.0f);   // pos0, o=2o2
        float a1 = fmaxf(fu.z + fv.z, 0.0f);   // pos1, o=2o2
        float b0 = fmaxf(fu.y + fv.y, 0.0f);   // pos0, o=2o2+1
        float b1 = fmaxf(fu.w + fv.w, 0.0f);   // pos1, o=2o2+1
        Hp[2 * o2]     = f2mul(pk2(a0, a1), ycp[2 * o2]);
        Hp[2 * o2 + 1] = f2mul(pk2(b0, b1), ycp[2 * o2 + 1]);
    }

    float s0 = s_bfin, s1 = s_bfin;
#pragma unroll
    for (int o2 = 0; o2 < 20; o2++) {
        const ulonglong2* wr = (const ulonglong2*)(s_wd + o2 * 20);
        u64 a = s_bcd[o2];
#pragma unroll
        for (int k = 0; k < 10; k++) {
            ulonglong2 w2 = wr[k];
            a = f2fma(w2.x, Hp[2 * k],     a);
            a = f2fma(w2.y, Hp[2 * k + 1], a);
        }
        float lo, hi;
        upk2(lo, hi, a);
        float wf = s_wfin[o2];
        s0 += fmaxf(lo, 0.0f) * wf;
        s1 += fmaxf(hi, 0.0f) * wf;
    }

    ((float2*)g_S)[(size_t)pair * Bh + bh] =
        make_float2(fmaxf(s0, 0.0f), fmaxf(s1, 0.0f));
}

// ---------------------------------------------------------------------------
// Kernel 3: block-staged 7-sum. Block handles 256 outputs = 1792 g_S floats
// = 448 float4s, loaded coalesced into smem (two guarded rounds cover
// indices 0..511 >= 448); per-thread stride-7 smem sum.
// ---------------------------------------------------------------------------
__global__ void __launch_bounds__(256, 8)
frap_k3(float* __restrict__ out, int n)
{
    __shared__ __align__(16) float s[1792];
    int tx = threadIdx.x;
    int obase = blockIdx.x * 256;
    size_t sbase = (size_t)obase * 7;

    const float4* g4 = (const float4*)(g_S + sbase);
    int lim = n * 7 - (int)sbase;                 // floats available
#pragma unroll
    for (int k = 0; k < 2; k++) {
        int idx = k * 256 + tx;                   // float4 index; 448 needed
        if (idx < 448 && idx * 4 < lim) {
            float4 v = g4[idx];
            float* d = &s[idx * 4];
            d[0] = v.x; d[1] = v.y; d[2] = v.z; d[3] = v.w;
        }
    }
    __syncthreads();

    int o = obase + tx;
    if (o >= n) return;
    const float* p = &s[tx * 7];
    out[o] = p[0] + p[1] + p[2] + p[3] + p[4] + p[5] + p[6];
}

// ---------------------------------------------------------------------------
extern "C" void kernel_launch(void* const* d_in, const int* in_sizes, int n_in,
                              void* d_out, int out_size)
{
    const float* fi        = (const float*)d_in[0];
    const float* emb_phase = (const float*)d_in[1];
    const float* w_veh     = (const float*)d_in[2];
    const float* b_veh     = (const float*)d_in[3];
    const float* w_line    = (const float*)d_in[4];
    const float* b_line    = (const float*)d_in[5];
    const float* emb_const = (const float*)d_in[6];
    const float* w_feat    = (const float*)d_in[7];
    const float* b_feat    = (const float*)d_in[8];
    const float* w_const   = (const float*)d_in[9];
    const float* b_const   = (const float*)d_in[10];
    const float* w_comb    = (const float*)d_in[11];
    const float* b_comb    = (const float*)d_in[12];
    const float* w_final   = (const float*)d_in[13];
    const float* b_final   = (const float*)d_in[14];
    const int*   cmask     = (const int*)d_in[15];

    int B = in_sizes[0] / 16;
    if (B > BMAX) B = BMAX;
    int Bh = B >> 1;

    dim3 grid1((B + 255) / 256, 8);
    dim3 grid2((Bh + 255) / 256, 56);
    int n = B * 8;
    int blocks3 = (n + 255) / 256;

    frap_k1<<<grid1, 256>>>(fi, emb_phase, w_veh, b_veh, w_line, b_line,
                            w_feat, b_feat, B);
    frap_k2<<<grid2, 256>>>(emb_const, w_const, b_const, w_comb, b_comb,
                            w_final, b_final, cmask, B);
    frap_k3<<<blocks3, 256>>>((float*)d_out, n);
}